// round 12
// baseline (speedup 1.0000x reference)
#include <cuda_runtime.h>
#include <cuda_bf16.h>
#include <cuda_fp16.h>
#include <math.h>
#include <cstdint>

#define N_TOK 8192
#define F_DIM 256
#define OUTD  64
#define NSPLIT 2
#define JCHUNK (N_TOK / NSPLIT)   /* 4096 */
#define M_TILE 128
#define JT 64                     /* j per tile */
#define NT_PER_CTA (JCHUNK / JT)  /* 64 tiles */
#define LOG2E 1.4426950408889634f

/* ---------------- scratch (no allocation allowed) ---------------- */
__device__ __half g_ftsT[OUTD * N_TOK];            /* [c][j] transposed f16 */
__device__ float g_f1[N_TOK];
__device__ float g_f2[N_TOK];
__device__ unsigned g_f2maxu = 0;                  /* ordered-uint max of f2 */
__device__ float g_acc[NSPLIT * N_TOK * OUTD];     /* 4 MB */
__device__ float g_den[NSPLIT * N_TOK];

/* ---------------- helpers ---------------- */
__device__ __forceinline__ uint32_t smem_u32(const void* p) {
    uint32_t a;
    asm("{ .reg .u64 t; cvta.to.shared.u64 t, %1; cvt.u32.u64 %0, t; }" : "=r"(a) : "l"(p));
    return a;
}
__device__ __forceinline__ uint32_t cvt2h(float a, float b) {
    uint32_t r;
    asm("cvt.rn.f16x2.f32 %0, %1, %2;" : "=r"(r) : "f"(b), "f"(a));
    return r;
}
__device__ __forceinline__ uint32_t cvt2bf(float a, float b) {
    uint32_t r;
    asm("cvt.rn.bf16x2.f32 %0, %1, %2;" : "=r"(r) : "f"(b), "f"(a));
    return r;
}
__device__ __forceinline__ float bf_lo_f(uint32_t h) { return __uint_as_float(h << 16); }
__device__ __forceinline__ float bf_hi_f(uint32_t h) { return __uint_as_float(h & 0xFFFF0000u); }
__device__ __forceinline__ uint32_t ex2h2(uint32_t x) {
    uint32_t r;
    asm("ex2.approx.f16x2 %0, %1;" : "=r"(r) : "r"(x));
    return r;
}
__device__ __forceinline__ void ldsm4(uint32_t& r0, uint32_t& r1, uint32_t& r2, uint32_t& r3,
                                      uint32_t addr) {
    asm volatile("ldmatrix.sync.aligned.m8n8.x4.shared.b16 {%0,%1,%2,%3}, [%4];"
                 : "=r"(r0), "=r"(r1), "=r"(r2), "=r"(r3) : "r"(addr));
}
__device__ __forceinline__ void mma16816(float* d, const uint32_t* a, uint32_t b0, uint32_t b1) {
    asm volatile("mma.sync.aligned.m16n8k16.row.col.f32.f16.f16.f32 "
                 "{%0,%1,%2,%3},{%4,%5,%6,%7},{%8,%9},{%0,%1,%2,%3};"
                 : "+f"(d[0]), "+f"(d[1]), "+f"(d[2]), "+f"(d[3])
                 : "r"(a[0]), "r"(a[1]), "r"(a[2]), "r"(a[3]), "r"(b0), "r"(b1));
}
__device__ __forceinline__ void mmabf(float* d, const uint32_t* a, uint32_t b0, uint32_t b1) {
    asm volatile("mma.sync.aligned.m16n8k16.row.col.f32.bf16.bf16.f32 "
                 "{%0,%1,%2,%3},{%4,%5,%6,%7},{%8,%9},{%0,%1,%2,%3};"
                 : "+f"(d[0]), "+f"(d[1]), "+f"(d[2]), "+f"(d[3])
                 : "r"(a[0]), "r"(a[1]), "r"(a[2]), "r"(a[3]), "r"(b0), "r"(b1));
}
__device__ __forceinline__ unsigned f2enc(float f) {
    unsigned u = __float_as_uint(f);
    return (u & 0x80000000u) ? ~u : (u | 0x80000000u);
}
__device__ __forceinline__ float f2dec(unsigned u) {
    unsigned b = (u & 0x80000000u) ? (u & 0x7FFFFFFFu) : ~u;
    return __uint_as_float(b);
}
#define BAR_SYNC512(id)   asm volatile("bar.sync %0, 512;"   :: "r"(id) : "memory")
#define BAR_ARRIVE512(id) asm volatile("bar.arrive %0, 512;" :: "r"(id) : "memory")
#define BAR_SYNC256(id)   asm volatile("bar.sync %0, 256;"   :: "r"(id) : "memory")

/* ------------------------------------------------------------------ */
/* k1: seq_fts = seq @ W1 via bf16x3 split HMMA (512 thr) — unchanged   */
/* ------------------------------------------------------------------ */
#define K1_AH 0
#define K1_AL 36864
#define K1_BH 73728
#define K1_BL 110592
#define K1_FTS 147456
#define K1_A1 155904
#define K1_A2 156160
#define K1_F1P 156416
#define K1_F2P 157440
#define SMEM1_BYTES 158464

__global__ __launch_bounds__(512, 1) void k1_fts(const float* __restrict__ seq,
        const float* __restrict__ W1, const float* __restrict__ a1,
        const float* __restrict__ b1, const float* __restrict__ a2,
        const float* __restrict__ b2) {
    extern __shared__ char sm[];
    const uint32_t sbase = smem_u32(sm);
    __shared__ unsigned lmax_s;

    const int tid = threadIdx.x;
    const int wid = tid >> 5, lane = tid & 31;
    const int rb  = blockIdx.x * 64;

    if (tid == 0) lmax_s = 0u;
    if (tid < OUTD) {
        ((float*)(sm + K1_A1))[tid] = a1[tid];
        ((float*)(sm + K1_A2))[tid] = a2[tid];
    }

#pragma unroll
    for (int i = 0; i < 8; ++i) {
        const int u = i * 512 + tid;
        const int m = u >> 6, ch = u & 63;
        const int kb = ch >> 4, kw = ch & 15;
        const float4 v = *((const float4*)(seq + (size_t)(rb + m) * F_DIM) + ch);
        const uint32_t h01 = cvt2bf(v.x, v.y), h23 = cvt2bf(v.z, v.w);
        const float e0 = v.x - bf_lo_f(h01), e1 = v.y - bf_hi_f(h01);
        const float e2 = v.z - bf_lo_f(h23), e3 = v.w - bf_hi_f(h23);
        char* dh = sm + K1_AH + kb * 9216 + m * 144 + kw * 8;
        char* dl = sm + K1_AL + kb * 9216 + m * 144 + kw * 8;
        *(uint2*)dh = make_uint2(h01, h23);
        *(uint2*)dl = make_uint2(cvt2bf(e0, e1), cvt2bf(e2, e3));
    }

#pragma unroll
    for (int i = 0; i < 4; ++i) {
        const int u = i * 512 + tid;
        const int n4 = u >> 7, k2g = u & 127;
        const int k = k2g * 2;
        const float4 v0 = *((const float4*)(W1 + (size_t)k * OUTD) + n4);
        const float4 v1 = *((const float4*)(W1 + (size_t)(k + 1) * OUTD) + n4);
        const int kb = k >> 6, koff = k & 63;
        const float* p0 = &v0.x;
        const float* p1 = &v1.x;
#pragma unroll
        for (int nn = 0; nn < 4; ++nn) {
            const int n = n4 * 4 + nn;
            const uint32_t h = cvt2bf(p0[nn], p1[nn]);
            const float e0 = p0[nn] - bf_lo_f(h), e1 = p1[nn] - bf_hi_f(h);
            *(uint32_t*)(sm + K1_BH + kb * 9216 + n * 144 + koff * 2) = h;
            *(uint32_t*)(sm + K1_BL + kb * 9216 + n * 144 + koff * 2) = cvt2bf(e0, e1);
        }
    }
    __syncthreads();

    const int rg  = (wid & 3) * 16;
    const int cgb = (wid >> 2) * 16;
    const uint32_t rsel = (uint32_t)(lane & 15) * 144 + (uint32_t)(lane >> 4) * 16;
    float acc[2][4];
#pragma unroll
    for (int n = 0; n < 2; ++n)
#pragma unroll
        for (int q = 0; q < 4; ++q) acc[n][q] = 0.f;

#pragma unroll
    for (int ks = 0; ks < 16; ++ks) {
        const uint32_t boff = (uint32_t)(ks >> 2) * 9216 + (uint32_t)(ks & 3) * 32;
        uint32_t ah[4], al[4], bh[4], bl[4];
        ldsm4(ah[0], ah[1], ah[2], ah[3], sbase + K1_AH + boff + rg * 144 + rsel);
        ldsm4(al[0], al[1], al[2], al[3], sbase + K1_AL + boff + rg * 144 + rsel);
        ldsm4(bh[0], bh[1], bh[2], bh[3], sbase + K1_BH + boff + cgb * 144 + rsel);
        ldsm4(bl[0], bl[1], bl[2], bl[3], sbase + K1_BL + boff + cgb * 144 + rsel);
        mmabf(acc[0], ah, bh[0], bh[2]);
        mmabf(acc[0], ah, bl[0], bl[2]);
        mmabf(acc[0], al, bh[0], bh[2]);
        mmabf(acc[1], ah, bh[1], bh[3]);
        mmabf(acc[1], ah, bl[1], bl[3]);
        mmabf(acc[1], al, bh[1], bh[3]);
    }

    const float* a1s = (const float*)(sm + K1_A1);
    const float* a2s = (const float*)(sm + K1_A2);
    float* f1p = (float*)(sm + K1_F1P);
    float* f2p = (float*)(sm + K1_F2P);
    const int r  = lane >> 2;
    const int cq = (lane & 3) * 2;

#pragma unroll
    for (int h = 0; h < 2; ++h) {
        const int m = rg + r + h * 8;
        float p1 = acc[0][2 * h] * a1s[cgb + cq] + acc[0][2 * h + 1] * a1s[cgb + cq + 1]
                 + acc[1][2 * h] * a1s[cgb + 8 + cq] + acc[1][2 * h + 1] * a1s[cgb + 8 + cq + 1];
        float p2 = acc[0][2 * h] * a2s[cgb + cq] + acc[0][2 * h + 1] * a2s[cgb + cq + 1]
                 + acc[1][2 * h] * a2s[cgb + 8 + cq] + acc[1][2 * h + 1] * a2s[cgb + 8 + cq + 1];
        p1 += __shfl_xor_sync(0xffffffffu, p1, 1);
        p1 += __shfl_xor_sync(0xffffffffu, p1, 2);
        p2 += __shfl_xor_sync(0xffffffffu, p2, 1);
        p2 += __shfl_xor_sync(0xffffffffu, p2, 2);
        if ((lane & 3) == 0) {
            f1p[(wid >> 2) * 64 + m] = p1;
            f2p[(wid >> 2) * 64 + m] = p2;
        }
        *(uint32_t*)(sm + K1_FTS + m * 132 + (cgb + cq) * 2) =
            cvt2h(acc[0][2 * h], acc[0][2 * h + 1]);
        *(uint32_t*)(sm + K1_FTS + m * 132 + (cgb + 8 + cq) * 2) =
            cvt2h(acc[1][2 * h], acc[1][2 * h + 1]);
    }
    __syncthreads();

    {
        const int c = tid >> 3, mg = tid & 7;
        uint32_t w[4];
#pragma unroll
        for (int p = 0; p < 4; ++p) {
            const uint32_t u0 = *(const uint16_t*)(sm + K1_FTS + (mg * 8 + 2 * p) * 132 + c * 2);
            const uint32_t u1 = *(const uint16_t*)(sm + K1_FTS + (mg * 8 + 2 * p + 1) * 132 + c * 2);
            w[p] = u0 | (u1 << 16);
        }
        *((uint4*)(g_ftsT + (size_t)c * N_TOK + rb + mg * 8)) = make_uint4(w[0], w[1], w[2], w[3]);
    }

    if (tid < 64) {
        const float f1 = f1p[tid] + f1p[64 + tid] + f1p[128 + tid] + f1p[192 + tid] + b1[0];
        const float f2 = f2p[tid] + f2p[64 + tid] + f2p[128 + tid] + f2p[192 + tid] + b2[0];
        g_f1[rb + tid] = f1;
        g_f2[rb + tid] = f2;
        atomicMax(&lmax_s, f2enc(f2));
    }
    __syncthreads();
    if (tid == 0) atomicMax(&g_f2maxu, lmax_s);
}

/* ------------------------------------------------------------------ */
/* k3: 512 threads: warps 0-7 produce P (bias via register-pipelined   */
/* direct LDG.128 — no smem round-trip), warps 8-15 consume (4x2       */
/* row/col split). 4-stage P ring.                                     */
/* ------------------------------------------------------------------ */
#define PSTRB 144                 /* bytes per smem tile row (72 f16) */
#define PSTG  18432               /* 128*144 */
#define PH_OFF 0                  /* 4 stages */
#define VH_OFF (4 * PSTG)         /* 73728: 80 rows x 144 = 11520 */
#define FCL_OFF 85248             /* 128 x float2 = 1024 */
#define SMEM3_BYTES 86528

__global__ __launch_bounds__(512, 1) void k3_attn(const float* __restrict__ bias) {
    extern __shared__ char sm[];
    const uint32_t sbase = smem_u32(sm);
    float2* fcl = (float2*)(sm + FCL_OFF);        /* {f1, -m*log2e} per row */

    const int tid  = threadIdx.x;
    const int wid  = tid >> 5, lane = tid & 31;
    const int ibase = blockIdx.x * M_TILE;
    const int s     = blockIdx.y;
    const int jbase0 = s * JCHUNK;

    if (tid < M_TILE) {
        const float f1v = g_f1[ibase + tid];
        const float f2m = f2dec(g_f2maxu);
        const float x = f1v + f2m;
        fcl[tid] = make_float2(f1v, -fmaxf(x, 0.2f * x) * LOG2E);
    }
    __syncthreads();

    if (wid < 8) {
        /* ===================== PRODUCERS (256 thr) ===================== */
        /* warp w owns rows w*16 .. w*16+15; bias pipelined in registers  */
        const int jq    = lane & 15;
        const int rhalf = lane >> 4;
        const float* browbase[8];
#pragma unroll
        for (int q = 0; q < 8; ++q)
            browbase[q] = bias + (size_t)(ibase + wid * 16 + q * 2 + rhalf) * N_TOK + jq * 4;

        /* prologue: bias regs + f2 vec for tile 0 */
        uint4 bv[8];
#pragma unroll
        for (int q = 0; q < 8; ++q)
            bv[q] = *(const uint4*)(browbase[q] + jbase0);
        float4 f2v = *((const float4*)(g_f2 + jbase0) + jq);

        int st4 = 0;
        for (int t = 0; t < NT_PER_CTA; ++t) {
            /* issue next tile's bias loads (clamped) + f2 */
            const int tn = (t + 1 < NT_PER_CTA) ? t + 1 : t;
            const int jbn = jbase0 + tn * JT;
            uint4 bvn[8];
#pragma unroll
            for (int q = 0; q < 8; ++q)
                bvn[q] = *(const uint4*)(browbase[q] + jbn);
            const float4 f2vn = *((const float4*)(g_f2 + jbn) + jq);

            if (t >= 4) BAR_SYNC512(5 + st4);        /* P stage empty (t-4 done) */

            /* generate P rows w*16..w*16+15: 64 j -> f16 via ex2.f16x2 */
            char* ph = sm + PH_OFF + st4 * PSTG;
#pragma unroll
            for (int k = 0; k < 8; ++k) {
                const int i = wid * 16 + k * 2 + rhalf;
                const float2 fc = fcl[i];
                const float4 bvf = *(const float4*)&bv[k];
                float x, t0, t1, t2, t3;
                x = fc.x + f2v.x; t0 = fmaxf(x, 0.2f * x);
                x = fc.x + f2v.y; t1 = fmaxf(x, 0.2f * x);
                x = fc.x + f2v.z; t2 = fmaxf(x, 0.2f * x);
                x = fc.x + f2v.w; t3 = fmaxf(x, 0.2f * x);
                const float g0 = fmaf(t0, LOG2E, fmaf(bvf.x, LOG2E, fc.y));
                const float g1 = fmaf(t1, LOG2E, fmaf(bvf.y, LOG2E, fc.y));
                const float g2 = fmaf(t2, LOG2E, fmaf(bvf.z, LOG2E, fc.y));
                const float g3 = fmaf(t3, LOG2E, fmaf(bvf.w, LOG2E, fc.y));
                *(uint2*)(ph + i * PSTRB + jq * 8) =
                    make_uint2(ex2h2(cvt2h(g0, g1)), ex2h2(cvt2h(g2, g3)));
            }
            BAR_ARRIVE512(1 + st4);                  /* signal P full */
#pragma unroll
            for (int q = 0; q < 8; ++q) bv[q] = bvn[q];
            f2v = f2vn;
            st4 = (st4 + 1) & 3;
        }
    } else {
        /* ===================== CONSUMERS (256 thr) ===================== */
        const int cw   = wid - 8;                    /* 0..7 */
        const int rg   = cw & 3;                     /* row group: 32 rows  */
        const int cg2  = cw >> 2;                    /* col group: 32 cols  */
        const int ctid = tid - 256;                  /* 0..255 */
        float acc[2][4][4];
        float accO[2][4];
#pragma unroll
        for (int b = 0; b < 2; ++b) {
#pragma unroll
            for (int n = 0; n < 4; ++n)
#pragma unroll
                for (int q = 0; q < 4; ++q) acc[b][n][q] = 0.f;
#pragma unroll
            for (int q = 0; q < 4; ++q) accO[b][q] = 0.f;
        }

        const uint32_t rsel = (uint32_t)(lane & 15) * PSTRB + (uint32_t)(lane >> 4) * 16;
        const uint32_t vhb = sbase + VH_OFF;

        /* init ones block: V rows 64..79 (col 64 = 1.0, cols 65..79 = 0) */
        for (int u = ctid; u < 16 * 36; u += 256) {
            const int r = u / 36, w = u % 36;
            ((uint32_t*)(sm + VH_OFF + (64 + r) * PSTRB))[w] = (r == 0) ? 0x3C003C00u : 0u;
        }

        int st4 = 0;
        for (int t = 0; t < NT_PER_CTA; ++t) {
            const int jb = jbase0 + t * JT;

            /* issue V loads early (latency hides under the full-wait) */
            uint4 vh_r[2];
#pragma unroll
            for (int r = 0; r < 2; ++r) {
                const int u = r * 256 + ctid;
                const int c = u >> 3, q = u & 7;
                vh_r[r] = *((const uint4*)(g_ftsT + (size_t)c * N_TOK + jb) + q);
            }

            BAR_SYNC512(1 + st4);                    /* P full */

            /* stage V into (single) smem buffer */
#pragma unroll
            for (int r = 0; r < 2; ++r) {
                const int u = r * 256 + ctid;
                const int c = u >> 3, q = u & 7;
                *(uint4*)(sm + VH_OFF + c * PSTRB + q * 16) = vh_r[r];
            }
            BAR_SYNC256(10);                         /* V (+ones) visible */

            const uint32_t ph = sbase + PH_OFF + st4 * PSTG;

#pragma unroll
            for (int ks = 0; ks < 4; ++ks) {
                const uint32_t kofs = (uint32_t)ks * 32;   /* 16 f16 = 32B */
                uint32_t ah0[4], ah1[4];
                ldsm4(ah0[0], ah0[1], ah0[2], ah0[3],
                      ph + (rg * 32) * PSTRB + kofs + rsel);
                ldsm4(ah1[0], ah1[1], ah1[2], ah1[3],
                      ph + (rg * 32 + 16) * PSTRB + kofs + rsel);
                uint32_t b0[4], b1[4];
                ldsm4(b0[0], b0[1], b0[2], b0[3],
                      vhb + ((cg2 * 2) * 16) * PSTRB + kofs + rsel);
                ldsm4(b1[0], b1[1], b1[2], b1[3],
                      vhb + ((cg2 * 2 + 1) * 16) * PSTRB + kofs + rsel);
                mma16816(acc[0][0], ah0, b0[0], b0[2]);
                mma16816(acc[0][1], ah0, b0[1], b0[3]);
                mma16816(acc[0][2], ah0, b1[0], b1[2]);
                mma16816(acc[0][3], ah0, b1[1], b1[3]);
                mma16816(acc[1][0], ah1, b0[0], b0[2]);
                mma16816(acc[1][1], ah1, b0[1], b0[3]);
                mma16816(acc[1][2], ah1, b1[0], b1[2]);
                mma16816(acc[1][3], ah1, b1[1], b1[3]);
                if (cg2 == 1) {                      /* ones block: row sums */
                    uint32_t bo[4];
                    ldsm4(bo[0], bo[1], bo[2], bo[3],
                          vhb + 64 * PSTRB + kofs + rsel);
                    mma16816(accO[0], ah0, bo[0], bo[2]);
                    mma16816(accO[1], ah1, bo[0], bo[2]);
                }
            }
            BAR_ARRIVE512(5 + st4);                  /* signal P empty */
            st4 = (st4 + 1) & 3;
        }

        /* write partials (rows rg*32.., cols cg2*32..) + denominators */
#pragma unroll
        for (int b = 0; b < 2; ++b) {
            const int m = rg * 32 + b * 16 + (lane >> 2);
            float* dst0 = g_acc + ((size_t)s * N_TOK + ibase + m) * OUTD;
            float* dst8 = dst0 + 8 * OUTD;
#pragma unroll
            for (int n = 0; n < 4; ++n) {
                const int c = cg2 * 32 + n * 8 + (lane & 3) * 2;
                *(float2*)(dst0 + c) = make_float2(acc[b][n][0], acc[b][n][1]);
                *(float2*)(dst8 + c) = make_float2(acc[b][n][2], acc[b][n][3]);
            }
            if (cg2 == 1 && (lane & 3) == 0) {
                g_den[(size_t)s * N_TOK + ibase + m]     = accO[b][0];
                g_den[(size_t)s * N_TOK + ibase + m + 8] = accO[b][2];
            }
        }
    }
}

/* ------------------------------------------------------------------ */
__global__ __launch_bounds__(256) void k4_combine(float* __restrict__ out) {
    const int idx = blockIdx.x * 256 + threadIdx.x;
    if (blockIdx.x == 0 && threadIdx.x == 0) g_f2maxu = 0u;  /* reset for next replay */
    if (idx >= N_TOK * 16) return;
    const int i = idx >> 4;
    float den = 0.f;
    float4 a = make_float4(0.f, 0.f, 0.f, 0.f);
#pragma unroll
    for (int s = 0; s < NSPLIT; ++s) {
        den += g_den[s * N_TOK + i];
        const float4 p = ((const float4*)g_acc)[(size_t)s * N_TOK * 16 + idx];
        a.x += p.x; a.y += p.y; a.z += p.z; a.w += p.w;
    }
    const float inv = 1.f / den;
    float4 r = make_float4(a.x * inv, a.y * inv, a.z * inv, a.w * inv);
    r.x = r.x > 0.f ? r.x : expm1f(r.x);
    r.y = r.y > 0.f ? r.y : expm1f(r.y);
    r.z = r.z > 0.f ? r.z : expm1f(r.z);
    r.w = r.w > 0.f ? r.w : expm1f(r.w);
    ((float4*)out)[idx] = r;
}

/* ------------------------------------------------------------------ */
extern "C" void kernel_launch(void* const* d_in, const int* in_sizes, int n_in,
                              void* d_out, int out_size) {
    const float* seq  = (const float*)d_in[0];
    const float* bias = (const float*)d_in[1];
    const float* W1   = (const float*)d_in[2];
    const float* a1   = (const float*)d_in[3];
    const float* b1   = (const float*)d_in[4];
    const float* a2   = (const float*)d_in[5];
    const float* b2   = (const float*)d_in[6];
    float* out = (float*)d_out;

    cudaFuncSetAttribute(k1_fts,  cudaFuncAttributeMaxDynamicSharedMemorySize, SMEM1_BYTES);
    cudaFuncSetAttribute(k3_attn, cudaFuncAttributeMaxDynamicSharedMemorySize, SMEM3_BYTES);

    k1_fts<<<128, 512, SMEM1_BYTES>>>(seq, W1, a1, b1, a2, b2);
    dim3 g3(N_TOK / M_TILE, NSPLIT);
    k3_attn<<<g3, 512, SMEM3_BYTES>>>(bias);
    k4_combine<<<(N_TOK * 16) / 256, 256>>>(out);
}

// round 13
// speedup vs baseline: 1.1157x; 1.1157x over previous
#include <cuda_runtime.h>
#include <cuda_bf16.h>
#include <cuda_fp16.h>
#include <math.h>
#include <cstdint>

#define N_TOK 8192
#define F_DIM 256
#define OUTD  64
#define NSPLIT 2
#define JCHUNK (N_TOK / NSPLIT)   /* 4096 */
#define M_TILE 128
#define JT 64                     /* j per tile */
#define NT_PER_CTA (JCHUNK / JT)  /* 64 tiles */
#define LOG2E 1.4426950408889634f

/* ---------------- scratch (no allocation allowed) ---------------- */
__device__ __half g_ftsT[OUTD * N_TOK];            /* [c][j] transposed f16 */
__device__ float g_f1[N_TOK];
__device__ float g_f2[N_TOK];
__device__ unsigned g_f2maxu = 0;                  /* ordered-uint max of f2 */
__device__ float g_acc[NSPLIT * N_TOK * OUTD];     /* 4 MB */
__device__ float g_den[NSPLIT * N_TOK];

/* ---------------- helpers ---------------- */
__device__ __forceinline__ uint32_t smem_u32(const void* p) {
    uint32_t a;
    asm("{ .reg .u64 t; cvta.to.shared.u64 t, %1; cvt.u32.u64 %0, t; }" : "=r"(a) : "l"(p));
    return a;
}
__device__ __forceinline__ uint32_t cvt2h(float a, float b) {
    uint32_t r;
    asm("cvt.rn.f16x2.f32 %0, %1, %2;" : "=r"(r) : "f"(b), "f"(a));
    return r;
}
__device__ __forceinline__ uint32_t cvt2bf(float a, float b) {
    uint32_t r;
    asm("cvt.rn.bf16x2.f32 %0, %1, %2;" : "=r"(r) : "f"(b), "f"(a));
    return r;
}
__device__ __forceinline__ float bf_lo_f(uint32_t h) { return __uint_as_float(h << 16); }
__device__ __forceinline__ float bf_hi_f(uint32_t h) { return __uint_as_float(h & 0xFFFF0000u); }
__device__ __forceinline__ uint32_t ex2h2(uint32_t x) {
    uint32_t r;
    asm("ex2.approx.f16x2 %0, %1;" : "=r"(r) : "r"(x));
    return r;
}
__device__ __forceinline__ void ldsm4(uint32_t& r0, uint32_t& r1, uint32_t& r2, uint32_t& r3,
                                      uint32_t addr) {
    asm volatile("ldmatrix.sync.aligned.m8n8.x4.shared.b16 {%0,%1,%2,%3}, [%4];"
                 : "=r"(r0), "=r"(r1), "=r"(r2), "=r"(r3) : "r"(addr));
}
__device__ __forceinline__ void mma16816(float* d, const uint32_t* a, uint32_t b0, uint32_t b1) {
    asm volatile("mma.sync.aligned.m16n8k16.row.col.f32.f16.f16.f32 "
                 "{%0,%1,%2,%3},{%4,%5,%6,%7},{%8,%9},{%0,%1,%2,%3};"
                 : "+f"(d[0]), "+f"(d[1]), "+f"(d[2]), "+f"(d[3])
                 : "r"(a[0]), "r"(a[1]), "r"(a[2]), "r"(a[3]), "r"(b0), "r"(b1));
}
__device__ __forceinline__ void mmabf(float* d, const uint32_t* a, uint32_t b0, uint32_t b1) {
    asm volatile("mma.sync.aligned.m16n8k16.row.col.f32.bf16.bf16.f32 "
                 "{%0,%1,%2,%3},{%4,%5,%6,%7},{%8,%9},{%0,%1,%2,%3};"
                 : "+f"(d[0]), "+f"(d[1]), "+f"(d[2]), "+f"(d[3])
                 : "r"(a[0]), "r"(a[1]), "r"(a[2]), "r"(a[3]), "r"(b0), "r"(b1));
}
__device__ __forceinline__ unsigned f2enc(float f) {
    unsigned u = __float_as_uint(f);
    return (u & 0x80000000u) ? ~u : (u | 0x80000000u);
}
__device__ __forceinline__ float f2dec(unsigned u) {
    unsigned b = (u & 0x80000000u) ? (u & 0x7FFFFFFFu) : ~u;
    return __uint_as_float(b);
}
#define BAR_SYNC512(id)   asm volatile("bar.sync %0, 512;"   :: "r"(id) : "memory")
#define BAR_ARRIVE512(id) asm volatile("bar.arrive %0, 512;" :: "r"(id) : "memory")
#define BAR_SYNC256(id)   asm volatile("bar.sync %0, 256;"   :: "r"(id) : "memory")
#define CP_ASYNC16(dst, src) \
    asm volatile("cp.async.cg.shared.global [%0], [%1], 16;" :: "r"(dst), "l"(src) : "memory")
#define CP_COMMIT() asm volatile("cp.async.commit_group;" ::: "memory")
#define CP_WAIT2()  asm volatile("cp.async.wait_group 2;" ::: "memory")

/* ------------------------------------------------------------------ */
/* k1: seq_fts = seq @ W1 via bf16x3 split HMMA (512 thr); conversion  */
/* loads FRONT-BATCHED into registers for high MLP; smem-staged        */
/* transposed f16 store; f1/f2 + global max(f2) fused.                 */
/* ------------------------------------------------------------------ */
#define K1_AH 0
#define K1_AL 36864
#define K1_BH 73728
#define K1_BL 110592
#define K1_FTS 147456
#define K1_A1 155904
#define K1_A2 156160
#define K1_F1P 156416
#define K1_F2P 157440
#define SMEM1_BYTES 158464

__global__ __launch_bounds__(512, 1) void k1_fts(const float* __restrict__ seq,
        const float* __restrict__ W1, const float* __restrict__ a1,
        const float* __restrict__ b1, const float* __restrict__ a2,
        const float* __restrict__ b2) {
    extern __shared__ char sm[];
    const uint32_t sbase = smem_u32(sm);
    __shared__ unsigned lmax_s;

    const int tid = threadIdx.x;
    const int wid = tid >> 5, lane = tid & 31;
    const int rb  = blockIdx.x * 64;

    if (tid == 0) lmax_s = 0u;
    if (tid < OUTD) {
        ((float*)(sm + K1_A1))[tid] = a1[tid];
        ((float*)(sm + K1_A2))[tid] = a2[tid];
    }

    /* A (seq tile 64x256) -> bf16 hi/lo; loads front-batched (4 at a time) */
#pragma unroll
    for (int g = 0; g < 2; ++g) {
        float4 va[4];
#pragma unroll
        for (int i = 0; i < 4; ++i) {
            const int u = (g * 4 + i) * 512 + tid;
            const int m = u >> 6, ch = u & 63;
            va[i] = *((const float4*)(seq + (size_t)(rb + m) * F_DIM) + ch);
        }
#pragma unroll
        for (int i = 0; i < 4; ++i) {
            const int u = (g * 4 + i) * 512 + tid;
            const int m = u >> 6, ch = u & 63;
            const int kb = ch >> 4, kw = ch & 15;
            const float4 v = va[i];
            const uint32_t h01 = cvt2bf(v.x, v.y), h23 = cvt2bf(v.z, v.w);
            const float e0 = v.x - bf_lo_f(h01), e1 = v.y - bf_hi_f(h01);
            const float e2 = v.z - bf_lo_f(h23), e3 = v.w - bf_hi_f(h23);
            char* dh = sm + K1_AH + kb * 9216 + m * 144 + kw * 8;
            char* dl = sm + K1_AL + kb * 9216 + m * 144 + kw * 8;
            *(uint2*)dh = make_uint2(h01, h23);
            *(uint2*)dl = make_uint2(cvt2bf(e0, e1), cvt2bf(e2, e3));
        }
    }

    /* B = W1^T -> bf16 hi/lo; loads front-batched (2 pairs at a time) */
#pragma unroll
    for (int g = 0; g < 2; ++g) {
        float4 w0[2], w1[2];
#pragma unroll
        for (int i = 0; i < 2; ++i) {
            const int u = (g * 2 + i) * 512 + tid;
            const int n4 = u >> 7, k2g = u & 127;
            const int k = k2g * 2;
            w0[i] = *((const float4*)(W1 + (size_t)k * OUTD) + n4);
            w1[i] = *((const float4*)(W1 + (size_t)(k + 1) * OUTD) + n4);
        }
#pragma unroll
        for (int i = 0; i < 2; ++i) {
            const int u = (g * 2 + i) * 512 + tid;
            const int n4 = u >> 7, k2g = u & 127;
            const int k = k2g * 2;
            const int kb = k >> 6, koff = k & 63;
            const float* p0 = &w0[i].x;
            const float* p1 = &w1[i].x;
#pragma unroll
            for (int nn = 0; nn < 4; ++nn) {
                const int n = n4 * 4 + nn;
                const uint32_t h = cvt2bf(p0[nn], p1[nn]);
                const float e0 = p0[nn] - bf_lo_f(h), e1 = p1[nn] - bf_hi_f(h);
                *(uint32_t*)(sm + K1_BH + kb * 9216 + n * 144 + koff * 2) = h;
                *(uint32_t*)(sm + K1_BL + kb * 9216 + n * 144 + koff * 2) = cvt2bf(e0, e1);
            }
        }
    }
    __syncthreads();

    const int rg  = (wid & 3) * 16;
    const int cgb = (wid >> 2) * 16;
    const uint32_t rsel = (uint32_t)(lane & 15) * 144 + (uint32_t)(lane >> 4) * 16;
    float acc[2][4];
#pragma unroll
    for (int n = 0; n < 2; ++n)
#pragma unroll
        for (int q = 0; q < 4; ++q) acc[n][q] = 0.f;

#pragma unroll
    for (int ks = 0; ks < 16; ++ks) {
        const uint32_t boff = (uint32_t)(ks >> 2) * 9216 + (uint32_t)(ks & 3) * 32;
        uint32_t ah[4], al[4], bh[4], bl[4];
        ldsm4(ah[0], ah[1], ah[2], ah[3], sbase + K1_AH + boff + rg * 144 + rsel);
        ldsm4(al[0], al[1], al[2], al[3], sbase + K1_AL + boff + rg * 144 + rsel);
        ldsm4(bh[0], bh[1], bh[2], bh[3], sbase + K1_BH + boff + cgb * 144 + rsel);
        ldsm4(bl[0], bl[1], bl[2], bl[3], sbase + K1_BL + boff + cgb * 144 + rsel);
        mmabf(acc[0], ah, bh[0], bh[2]);
        mmabf(acc[0], ah, bl[0], bl[2]);
        mmabf(acc[0], al, bh[0], bh[2]);
        mmabf(acc[1], ah, bh[1], bh[3]);
        mmabf(acc[1], ah, bl[1], bl[3]);
        mmabf(acc[1], al, bh[1], bh[3]);
    }

    const float* a1s = (const float*)(sm + K1_A1);
    const float* a2s = (const float*)(sm + K1_A2);
    float* f1p = (float*)(sm + K1_F1P);
    float* f2p = (float*)(sm + K1_F2P);
    const int r  = lane >> 2;
    const int cq = (lane & 3) * 2;

#pragma unroll
    for (int h = 0; h < 2; ++h) {
        const int m = rg + r + h * 8;
        float p1 = acc[0][2 * h] * a1s[cgb + cq] + acc[0][2 * h + 1] * a1s[cgb + cq + 1]
                 + acc[1][2 * h] * a1s[cgb + 8 + cq] + acc[1][2 * h + 1] * a1s[cgb + 8 + cq + 1];
        float p2 = acc[0][2 * h] * a2s[cgb + cq] + acc[0][2 * h + 1] * a2s[cgb + cq + 1]
                 + acc[1][2 * h] * a2s[cgb + 8 + cq] + acc[1][2 * h + 1] * a2s[cgb + 8 + cq + 1];
        p1 += __shfl_xor_sync(0xffffffffu, p1, 1);
        p1 += __shfl_xor_sync(0xffffffffu, p1, 2);
        p2 += __shfl_xor_sync(0xffffffffu, p2, 1);
        p2 += __shfl_xor_sync(0xffffffffu, p2, 2);
        if ((lane & 3) == 0) {
            f1p[(wid >> 2) * 64 + m] = p1;
            f2p[(wid >> 2) * 64 + m] = p2;
        }
        *(uint32_t*)(sm + K1_FTS + m * 132 + (cgb + cq) * 2) =
            cvt2h(acc[0][2 * h], acc[0][2 * h + 1]);
        *(uint32_t*)(sm + K1_FTS + m * 132 + (cgb + 8 + cq) * 2) =
            cvt2h(acc[1][2 * h], acc[1][2 * h + 1]);
    }
    __syncthreads();

    {
        const int c = tid >> 3, mg = tid & 7;
        uint32_t w[4];
#pragma unroll
        for (int p = 0; p < 4; ++p) {
            const uint32_t u0 = *(const uint16_t*)(sm + K1_FTS + (mg * 8 + 2 * p) * 132 + c * 2);
            const uint32_t u1 = *(const uint16_t*)(sm + K1_FTS + (mg * 8 + 2 * p + 1) * 132 + c * 2);
            w[p] = u0 | (u1 << 16);
        }
        *((uint4*)(g_ftsT + (size_t)c * N_TOK + rb + mg * 8)) = make_uint4(w[0], w[1], w[2], w[3]);
    }

    if (tid < 64) {
        const float f1 = f1p[tid] + f1p[64 + tid] + f1p[128 + tid] + f1p[192 + tid] + b1[0];
        const float f2 = f2p[tid] + f2p[64 + tid] + f2p[128 + tid] + f2p[192 + tid] + b2[0];
        g_f1[rb + tid] = f1;
        g_f2[rb + tid] = f2;
        atomicMax(&lmax_s, f2enc(f2));
    }
    __syncthreads();
    if (tid == 0) atomicMax(&g_f2maxu, lmax_s);
}

/* ------------------------------------------------------------------ */
/* k3 (reverted to R11 design): 512 threads; warps 0-7 produce P       */
/* (per-warp-owned bias rows via cp.async ring + ex2.f16x2), warps     */
/* 8-15 consume (4x2 row/col split). 3-stage P ring, 4-slot bias ring. */
/* ------------------------------------------------------------------ */
#define PSTRB 144                 /* bytes per smem tile row (72 f16) */
#define PSTG  18432               /* 128*144 */
#define PH_OFF 0                  /* 3 stages */
#define VH_OFF (3 * PSTG)         /* 55296: 80 rows x 144 = 11520 */
#define FCL_OFF 66816             /* 128 x float2 = 1024 */
#define BIAS_OFF 67840            /* 4 stages x 32768 */
#define BIAS_STG 32768
#define SMEM3_BYTES (BIAS_OFF + 4 * BIAS_STG)   /* 198912 */

__global__ __launch_bounds__(512, 1) void k3_attn(const float* __restrict__ bias) {
    extern __shared__ char sm[];
    const uint32_t sbase = smem_u32(sm);
    float2* fcl = (float2*)(sm + FCL_OFF);        /* {f1, -m*log2e} per row */

    const int tid  = threadIdx.x;
    const int wid  = tid >> 5, lane = tid & 31;
    const int ibase = blockIdx.x * M_TILE;
    const int s     = blockIdx.y;
    const int jbase0 = s * JCHUNK;

    if (tid < M_TILE) {
        const float f1v = g_f1[ibase + tid];
        const float f2m = f2dec(g_f2maxu);
        const float x = f1v + f2m;
        fcl[tid] = make_float2(f1v, -fmaxf(x, 0.2f * x) * LOG2E);
    }
    __syncthreads();

    if (wid < 8) {
        /* ===================== PRODUCERS (256 thr) ===================== */
        /* warp w owns bias/P rows w*16 .. w*16+15 (within-warp pipeline)  */
        const int jq    = lane & 15;
        const int rhalf = lane >> 4;

        /* prologue: prefetch bias tiles 0,1,2 (warp-owned rows) */
#pragma unroll
        for (int pt = 0; pt < 3; ++pt) {
            const int jb2 = jbase0 + pt * JT;
            const uint32_t dbase = sbase + BIAS_OFF + pt * BIAS_STG;
#pragma unroll
            for (int q = 0; q < 8; ++q) {
                const int row = wid * 16 + q * 2 + rhalf;
                CP_ASYNC16(dbase + row * 256 + jq * 16,
                           bias + (size_t)(ibase + row) * N_TOK + jb2 + jq * 4);
            }
            CP_COMMIT();
        }

        int st3 = 0;
        for (int t = 0; t < NT_PER_CTA; ++t) {
            const int jb = jbase0 + t * JT;
            if (t >= 3) BAR_SYNC512(4 + st3);        /* P stage empty (t-3 done) */

            CP_WAIT2();                               /* own bias rows for tile t */
            __syncwarp();                             /* cross-lane visibility */

            /* prefetch bias tile t+3 (own rows; slot reuse is within-warp) */
            if (t + 3 < NT_PER_CTA) {
                const int slot = (t + 3) & 3;
                const int jb2 = jbase0 + (t + 3) * JT;
                const uint32_t dbase = sbase + BIAS_OFF + slot * BIAS_STG;
#pragma unroll
                for (int q = 0; q < 8; ++q) {
                    const int row = wid * 16 + q * 2 + rhalf;
                    CP_ASYNC16(dbase + row * 256 + jq * 16,
                               bias + (size_t)(ibase + row) * N_TOK + jb2 + jq * 4);
                }
            }
            CP_COMMIT();

            /* generate P rows w*16..w*16+15: 64 j -> f16 via ex2.f16x2 */
            char* ph = sm + PH_OFF + st3 * PSTG;
            const char* bslot = sm + BIAS_OFF + (t & 3) * BIAS_STG;
            const float4 f2v = *((const float4*)(g_f2 + jb) + jq);
#pragma unroll
            for (int k = 0; k < 8; ++k) {
                const int i = wid * 16 + k * 2 + rhalf;
                const float2 fc = fcl[i];
                const float4 bv = *(const float4*)(bslot + i * 256 + jq * 16);
                float x, t0, t1, t2, t3;
                x = fc.x + f2v.x; t0 = fmaxf(x, 0.2f * x);
                x = fc.x + f2v.y; t1 = fmaxf(x, 0.2f * x);
                x = fc.x + f2v.z; t2 = fmaxf(x, 0.2f * x);
                x = fc.x + f2v.w; t3 = fmaxf(x, 0.2f * x);
                const float g0 = fmaf(t0, LOG2E, fmaf(bv.x, LOG2E, fc.y));
                const float g1 = fmaf(t1, LOG2E, fmaf(bv.y, LOG2E, fc.y));
                const float g2 = fmaf(t2, LOG2E, fmaf(bv.z, LOG2E, fc.y));
                const float g3 = fmaf(t3, LOG2E, fmaf(bv.w, LOG2E, fc.y));
                *(uint2*)(ph + i * PSTRB + jq * 8) =
                    make_uint2(ex2h2(cvt2h(g0, g1)), ex2h2(cvt2h(g2, g3)));
            }
            BAR_ARRIVE512(1 + st3);                  /* signal P full */
            if (++st3 == 3) st3 = 0;
        }
    } else {
        /* ===================== CONSUMERS (256 thr) ===================== */
        const int cw   = wid - 8;                    /* 0..7 */
        const int rg   = cw & 3;                     /* row group: 32 rows  */
        const int cg2  = cw >> 2;                    /* col group: 32 cols  */
        const int ctid = tid - 256;                  /* 0..255 */
        float acc[2][4][4];
        float accO[2][4];
#pragma unroll
        for (int b = 0; b < 2; ++b) {
#pragma unroll
            for (int n = 0; n < 4; ++n)
#pragma unroll
                for (int q = 0; q < 4; ++q) acc[b][n][q] = 0.f;
#pragma unroll
            for (int q = 0; q < 4; ++q) accO[b][q] = 0.f;
        }

        const uint32_t rsel = (uint32_t)(lane & 15) * PSTRB + (uint32_t)(lane >> 4) * 16;
        const uint32_t vhb = sbase + VH_OFF;

        /* init ones block: V rows 64..79 (col 64 = 1.0, cols 65..79 = 0) */
        for (int u = ctid; u < 16 * 36; u += 256) {
            const int r = u / 36, w = u % 36;
            ((uint32_t*)(sm + VH_OFF + (64 + r) * PSTRB))[w] = (r == 0) ? 0x3C003C00u : 0u;
        }

        int st3 = 0;
        for (int t = 0; t < NT_PER_CTA; ++t) {
            const int jb = jbase0 + t * JT;

            /* issue V loads early (latency hides under the full-wait) */
            uint4 vh_r[2];
#pragma unroll
            for (int r = 0; r < 2; ++r) {
                const int u = r * 256 + ctid;
                const int c = u >> 3, q = u & 7;
                vh_r[r] = *((const uint4*)(g_ftsT + (size_t)c * N_TOK + jb) + q);
            }

            BAR_SYNC512(1 + st3);                    /* P full */

            /* stage V into (single) smem buffer */
#pragma unroll
            for (int r = 0; r < 2; ++r) {
                const int u = r * 256 + ctid;
                const int c = u >> 3, q = u & 7;
                *(uint4*)(sm + VH_OFF + c * PSTRB + q * 16) = vh_r[r];
            }
            BAR_SYNC256(8);                          /* V (+ones) visible */

            const uint32_t ph = sbase + PH_OFF + st3 * PSTG;

#pragma unroll
            for (int ks = 0; ks < 4; ++ks) {
                const uint32_t kofs = (uint32_t)ks * 32;   /* 16 f16 = 32B */
                uint32_t ah0[4], ah1[4];
                ldsm4(ah0[0], ah0[1], ah0[2], ah0[3],
                      ph + (rg * 32) * PSTRB + kofs + rsel);
                ldsm4(ah1[0], ah1[1], ah1[2], ah1[3],
                      ph + (rg * 32 + 16) * PSTRB + kofs + rsel);
                uint32_t b0[4], b1[4];
                ldsm4(b0[0], b0[1], b0[2], b0[3],
                      vhb + ((cg2 * 2) * 16) * PSTRB + kofs + rsel);
                ldsm4(b1[0], b1[1], b1[2], b1[3],
                      vhb + ((cg2 * 2 + 1) * 16) * PSTRB + kofs + rsel);
                mma16816(acc[0][0], ah0, b0[0], b0[2]);
                mma16816(acc[0][1], ah0, b0[1], b0[3]);
                mma16816(acc[0][2], ah0, b1[0], b1[2]);
                mma16816(acc[0][3], ah0, b1[1], b1[3]);
                mma16816(acc[1][0], ah1, b0[0], b0[2]);
                mma16816(acc[1][1], ah1, b0[1], b0[3]);
                mma16816(acc[1][2], ah1, b1[0], b1[2]);
                mma16816(acc[1][3], ah1, b1[1], b1[3]);
                if (cg2 == 1) {                      /* ones block: row sums */
                    uint32_t bo[4];
                    ldsm4(bo[0], bo[1], bo[2], bo[3],
                          vhb + 64 * PSTRB + kofs + rsel);
                    mma16816(accO[0], ah0, bo[0], bo[2]);
                    mma16816(accO[1], ah1, bo[0], bo[2]);
                }
            }
            BAR_ARRIVE512(4 + st3);                  /* signal P empty */
            if (++st3 == 3) st3 = 0;
        }

        /* write partials (rows rg*32.., cols cg2*32..) + denominators */
#pragma unroll
        for (int b = 0; b < 2; ++b) {
            const int m = rg * 32 + b * 16 + (lane >> 2);
            float* dst0 = g_acc + ((size_t)s * N_TOK + ibase + m) * OUTD;
            float* dst8 = dst0 + 8 * OUTD;
#pragma unroll
            for (int n = 0; n < 4; ++n) {
                const int c = cg2 * 32 + n * 8 + (lane & 3) * 2;
                *(float2*)(dst0 + c) = make_float2(acc[b][n][0], acc[b][n][1]);
                *(float2*)(dst8 + c) = make_float2(acc[b][n][2], acc[b][n][3]);
            }
            if (cg2 == 1 && (lane & 3) == 0) {
                g_den[(size_t)s * N_TOK + ibase + m]     = accO[b][0];
                g_den[(size_t)s * N_TOK + ibase + m + 8] = accO[b][2];
            }
        }
    }
}

/* ------------------------------------------------------------------ */
__global__ __launch_bounds__(256) void k4_combine(float* __restrict__ out) {
    const int idx = blockIdx.x * 256 + threadIdx.x;
    if (blockIdx.x == 0 && threadIdx.x == 0) g_f2maxu = 0u;  /* reset for next replay */
    if (idx >= N_TOK * 16) return;
    const int i = idx >> 4;
    float den = 0.f;
    float4 a = make_float4(0.f, 0.f, 0.f, 0.f);
#pragma unroll
    for (int s = 0; s < NSPLIT; ++s) {
        den += g_den[s * N_TOK + i];
        const float4 p = ((const float4*)g_acc)[(size_t)s * N_TOK * 16 + idx];
        a.x += p.x; a.y += p.y; a.z += p.z; a.w += p.w;
    }
    const float inv = 1.f / den;
    float4 r = make_float4(a.x * inv, a.y * inv, a.z * inv, a.w * inv);
    r.x = r.x > 0.f ? r.x : expm1f(r.x);
    r.y = r.y > 0.f ? r.y : expm1f(r.y);
    r.z = r.z > 0.f ? r.z : expm1f(r.z);
    r.w = r.w > 0.f ? r.w : expm1f(r.w);
    ((float4*)out)[idx] = r;
}

/* ------------------------------------------------------------------ */
extern "C" void kernel_launch(void* const* d_in, const int* in_sizes, int n_in,
                              void* d_out, int out_size) {
    const float* seq  = (const float*)d_in[0];
    const float* bias = (const float*)d_in[1];
    const float* W1   = (const float*)d_in[2];
    const float* a1   = (const float*)d_in[3];
    const float* b1   = (const float*)d_in[4];
    const float* a2   = (const float*)d_in[5];
    const float* b2   = (const float*)d_in[6];
    float* out = (float*)d_out;

    cudaFuncSetAttribute(k1_fts,  cudaFuncAttributeMaxDynamicSharedMemorySize, SMEM1_BYTES);
    cudaFuncSetAttribute(k3_attn, cudaFuncAttributeMaxDynamicSharedMemorySize, SMEM3_BYTES);

    k1_fts<<<128, 512, SMEM1_BYTES>>>(seq, W1, a1, b1, a2, b2);
    dim3 g3(N_TOK / M_TILE, NSPLIT);
    k3_attn<<<g3, 512, SMEM3_BYTES>>>(bias);
    k4_combine<<<(N_TOK * 16) / 256, 256>>>(out);
}

// round 14
// speedup vs baseline: 1.2827x; 1.1497x over previous
#include <cuda_runtime.h>
#include <cuda_bf16.h>
#include <cuda_fp16.h>
#include <math.h>
#include <cstdint>

#define N_TOK 8192
#define F_DIM 256
#define OUTD  64
#define NSPLIT 2
#define JCHUNK (N_TOK / NSPLIT)   /* 4096 */
#define M_TILE 128
#define JT 128                    /* j per tile */
#define NT_PER_CTA (JCHUNK / JT)  /* 32 tiles */
#define LOG2E 1.4426950408889634f

/* ---------------- scratch (no allocation allowed) ---------------- */
__device__ __half g_ftsT[OUTD * N_TOK];            /* [c][j] transposed f16 */
__device__ float g_f1[N_TOK];
__device__ float g_f2[N_TOK];
__device__ unsigned g_f2maxu = 0;                  /* ordered-uint max of f2 */
__device__ float g_acc[NSPLIT * N_TOK * OUTD];     /* 4 MB */
__device__ float g_den[NSPLIT * N_TOK];

/* ---------------- helpers ---------------- */
__device__ __forceinline__ uint32_t smem_u32(const void* p) {
    uint32_t a;
    asm("{ .reg .u64 t; cvta.to.shared.u64 t, %1; cvt.u32.u64 %0, t; }" : "=r"(a) : "l"(p));
    return a;
}
__device__ __forceinline__ uint32_t cvt2h(float a, float b) {
    uint32_t r;
    asm("cvt.rn.f16x2.f32 %0, %1, %2;" : "=r"(r) : "f"(b), "f"(a));
    return r;
}
__device__ __forceinline__ uint32_t cvt2bf(float a, float b) {
    uint32_t r;
    asm("cvt.rn.bf16x2.f32 %0, %1, %2;" : "=r"(r) : "f"(b), "f"(a));
    return r;
}
__device__ __forceinline__ float bf_lo_f(uint32_t h) { return __uint_as_float(h << 16); }
__device__ __forceinline__ float bf_hi_f(uint32_t h) { return __uint_as_float(h & 0xFFFF0000u); }
__device__ __forceinline__ uint32_t ex2h2(uint32_t x) {
    uint32_t r;
    asm("ex2.approx.f16x2 %0, %1;" : "=r"(r) : "r"(x));
    return r;
}
__device__ __forceinline__ void ldsm4(uint32_t& r0, uint32_t& r1, uint32_t& r2, uint32_t& r3,
                                      uint32_t addr) {
    asm volatile("ldmatrix.sync.aligned.m8n8.x4.shared.b16 {%0,%1,%2,%3}, [%4];"
                 : "=r"(r0), "=r"(r1), "=r"(r2), "=r"(r3) : "r"(addr));
}
__device__ __forceinline__ void mma16816(float* d, const uint32_t* a, uint32_t b0, uint32_t b1) {
    asm volatile("mma.sync.aligned.m16n8k16.row.col.f32.f16.f16.f32 "
                 "{%0,%1,%2,%3},{%4,%5,%6,%7},{%8,%9},{%0,%1,%2,%3};"
                 : "+f"(d[0]), "+f"(d[1]), "+f"(d[2]), "+f"(d[3])
                 : "r"(a[0]), "r"(a[1]), "r"(a[2]), "r"(a[3]), "r"(b0), "r"(b1));
}
__device__ __forceinline__ void mmabf(float* d, const uint32_t* a, uint32_t b0, uint32_t b1) {
    asm volatile("mma.sync.aligned.m16n8k16.row.col.f32.bf16.bf16.f32 "
                 "{%0,%1,%2,%3},{%4,%5,%6,%7},{%8,%9},{%0,%1,%2,%3};"
                 : "+f"(d[0]), "+f"(d[1]), "+f"(d[2]), "+f"(d[3])
                 : "r"(a[0]), "r"(a[1]), "r"(a[2]), "r"(a[3]), "r"(b0), "r"(b1));
}
__device__ __forceinline__ unsigned f2enc(float f) {
    unsigned u = __float_as_uint(f);
    return (u & 0x80000000u) ? ~u : (u | 0x80000000u);
}
__device__ __forceinline__ float f2dec(unsigned u) {
    unsigned b = (u & 0x80000000u) ? (u & 0x7FFFFFFFu) : ~u;
    return __uint_as_float(b);
}
#define BAR_SYNC512(id)   asm volatile("bar.sync %0, 512;"   :: "r"(id) : "memory")
#define BAR_ARRIVE512(id) asm volatile("bar.arrive %0, 512;" :: "r"(id) : "memory")
#define BAR_SYNC256(id)   asm volatile("bar.sync %0, 256;"   :: "r"(id) : "memory")
#define CP_ASYNC16(dst, src) \
    asm volatile("cp.async.cg.shared.global [%0], [%1], 16;" :: "r"(dst), "l"(src) : "memory")
#define CP_COMMIT() asm volatile("cp.async.commit_group;" ::: "memory")
#define CP_WAIT1()  asm volatile("cp.async.wait_group 1;" ::: "memory")

/* ------------------------------------------------------------------ */
/* k1: seq_fts = seq @ W1 via bf16x3 split HMMA (512 thr) — unchanged   */
/* ------------------------------------------------------------------ */
#define K1_AH 0
#define K1_AL 36864
#define K1_BH 73728
#define K1_BL 110592
#define K1_FTS 147456
#define K1_A1 155904
#define K1_A2 156160
#define K1_F1P 156416
#define K1_F2P 157440
#define SMEM1_BYTES 158464

__global__ __launch_bounds__(512, 1) void k1_fts(const float* __restrict__ seq,
        const float* __restrict__ W1, const float* __restrict__ a1,
        const float* __restrict__ b1, const float* __restrict__ a2,
        const float* __restrict__ b2) {
    extern __shared__ char sm[];
    const uint32_t sbase = smem_u32(sm);
    __shared__ unsigned lmax_s;

    const int tid = threadIdx.x;
    const int wid = tid >> 5, lane = tid & 31;
    const int rb  = blockIdx.x * 64;

    if (tid == 0) lmax_s = 0u;
    if (tid < OUTD) {
        ((float*)(sm + K1_A1))[tid] = a1[tid];
        ((float*)(sm + K1_A2))[tid] = a2[tid];
    }

#pragma unroll
    for (int i = 0; i < 8; ++i) {
        const int u = i * 512 + tid;
        const int m = u >> 6, ch = u & 63;
        const int kb = ch >> 4, kw = ch & 15;
        const float4 v = *((const float4*)(seq + (size_t)(rb + m) * F_DIM) + ch);
        const uint32_t h01 = cvt2bf(v.x, v.y), h23 = cvt2bf(v.z, v.w);
        const float e0 = v.x - bf_lo_f(h01), e1 = v.y - bf_hi_f(h01);
        const float e2 = v.z - bf_lo_f(h23), e3 = v.w - bf_hi_f(h23);
        char* dh = sm + K1_AH + kb * 9216 + m * 144 + kw * 8;
        char* dl = sm + K1_AL + kb * 9216 + m * 144 + kw * 8;
        *(uint2*)dh = make_uint2(h01, h23);
        *(uint2*)dl = make_uint2(cvt2bf(e0, e1), cvt2bf(e2, e3));
    }

#pragma unroll
    for (int i = 0; i < 4; ++i) {
        const int u = i * 512 + tid;
        const int n4 = u >> 7, k2g = u & 127;
        const int k = k2g * 2;
        const float4 v0 = *((const float4*)(W1 + (size_t)k * OUTD) + n4);
        const float4 v1 = *((const float4*)(W1 + (size_t)(k + 1) * OUTD) + n4);
        const int kb = k >> 6, koff = k & 63;
        const float* p0 = &v0.x;
        const float* p1 = &v1.x;
#pragma unroll
        for (int nn = 0; nn < 4; ++nn) {
            const int n = n4 * 4 + nn;
            const uint32_t h = cvt2bf(p0[nn], p1[nn]);
            const float e0 = p0[nn] - bf_lo_f(h), e1 = p1[nn] - bf_hi_f(h);
            *(uint32_t*)(sm + K1_BH + kb * 9216 + n * 144 + koff * 2) = h;
            *(uint32_t*)(sm + K1_BL + kb * 9216 + n * 144 + koff * 2) = cvt2bf(e0, e1);
        }
    }
    __syncthreads();

    const int rg  = (wid & 3) * 16;
    const int cgb = (wid >> 2) * 16;
    const uint32_t rsel = (uint32_t)(lane & 15) * 144 + (uint32_t)(lane >> 4) * 16;
    float acc[2][4];
#pragma unroll
    for (int n = 0; n < 2; ++n)
#pragma unroll
        for (int q = 0; q < 4; ++q) acc[n][q] = 0.f;

#pragma unroll
    for (int ks = 0; ks < 16; ++ks) {
        const uint32_t boff = (uint32_t)(ks >> 2) * 9216 + (uint32_t)(ks & 3) * 32;
        uint32_t ah[4], al[4], bh[4], bl[4];
        ldsm4(ah[0], ah[1], ah[2], ah[3], sbase + K1_AH + boff + rg * 144 + rsel);
        ldsm4(al[0], al[1], al[2], al[3], sbase + K1_AL + boff + rg * 144 + rsel);
        ldsm4(bh[0], bh[1], bh[2], bh[3], sbase + K1_BH + boff + cgb * 144 + rsel);
        ldsm4(bl[0], bl[1], bl[2], bl[3], sbase + K1_BL + boff + cgb * 144 + rsel);
        mmabf(acc[0], ah, bh[0], bh[2]);
        mmabf(acc[0], ah, bl[0], bl[2]);
        mmabf(acc[0], al, bh[0], bh[2]);
        mmabf(acc[1], ah, bh[1], bh[3]);
        mmabf(acc[1], ah, bl[1], bl[3]);
        mmabf(acc[1], al, bh[1], bh[3]);
    }

    const float* a1s = (const float*)(sm + K1_A1);
    const float* a2s = (const float*)(sm + K1_A2);
    float* f1p = (float*)(sm + K1_F1P);
    float* f2p = (float*)(sm + K1_F2P);
    const int r  = lane >> 2;
    const int cq = (lane & 3) * 2;

#pragma unroll
    for (int h = 0; h < 2; ++h) {
        const int m = rg + r + h * 8;
        float p1 = acc[0][2 * h] * a1s[cgb + cq] + acc[0][2 * h + 1] * a1s[cgb + cq + 1]
                 + acc[1][2 * h] * a1s[cgb + 8 + cq] + acc[1][2 * h + 1] * a1s[cgb + 8 + cq + 1];
        float p2 = acc[0][2 * h] * a2s[cgb + cq] + acc[0][2 * h + 1] * a2s[cgb + cq + 1]
                 + acc[1][2 * h] * a2s[cgb + 8 + cq] + acc[1][2 * h + 1] * a2s[cgb + 8 + cq + 1];
        p1 += __shfl_xor_sync(0xffffffffu, p1, 1);
        p1 += __shfl_xor_sync(0xffffffffu, p1, 2);
        p2 += __shfl_xor_sync(0xffffffffu, p2, 1);
        p2 += __shfl_xor_sync(0xffffffffu, p2, 2);
        if ((lane & 3) == 0) {
            f1p[(wid >> 2) * 64 + m] = p1;
            f2p[(wid >> 2) * 64 + m] = p2;
        }
        *(uint32_t*)(sm + K1_FTS + m * 132 + (cgb + cq) * 2) =
            cvt2h(acc[0][2 * h], acc[0][2 * h + 1]);
        *(uint32_t*)(sm + K1_FTS + m * 132 + (cgb + 8 + cq) * 2) =
            cvt2h(acc[1][2 * h], acc[1][2 * h + 1]);
    }
    __syncthreads();

    {
        const int c = tid >> 3, mg = tid & 7;
        uint32_t w[4];
#pragma unroll
        for (int p = 0; p < 4; ++p) {
            const uint32_t u0 = *(const uint16_t*)(sm + K1_FTS + (mg * 8 + 2 * p) * 132 + c * 2);
            const uint32_t u1 = *(const uint16_t*)(sm + K1_FTS + (mg * 8 + 2 * p + 1) * 132 + c * 2);
            w[p] = u0 | (u1 << 16);
        }
        *((uint4*)(g_ftsT + (size_t)c * N_TOK + rb + mg * 8)) = make_uint4(w[0], w[1], w[2], w[3]);
    }

    if (tid < 64) {
        const float f1 = f1p[tid] + f1p[64 + tid] + f1p[128 + tid] + f1p[192 + tid] + b1[0];
        const float f2 = f2p[tid] + f2p[64 + tid] + f2p[128 + tid] + f2p[192 + tid] + b2[0];
        g_f1[rb + tid] = f1;
        g_f2[rb + tid] = f2;
        atomicMax(&lmax_s, f2enc(f2));
    }
    __syncthreads();
    if (tid == 0) atomicMax(&g_f2maxu, lmax_s);
}

/* ------------------------------------------------------------------ */
/* k3: JT=128 tiles (32 per CTA). 512 threads: warps 0-7 produce P     */
/* (per-warp bias rows via 2-slot cp.async ring), warps 8-15 consume   */
/* (4x2 row/col split, 8 ksteps). 2-stage P ring.                      */
/* ------------------------------------------------------------------ */
#define PSTRB 272                 /* bytes per smem tile row (136 f16) */
#define PSTG  (128 * PSTRB)       /* 34816 */
#define PH_OFF 0                  /* 2 stages */
#define VH_OFF (2 * PSTG)         /* 69632: 80 rows x 272 = 21760 */
#define FCL_OFF 91392             /* 128 x float2 = 1024 */
#define BIAS_OFF 92416            /* 2 slots x 65536 */
#define BIAS_STG 65536
#define SMEM3_BYTES (BIAS_OFF + 2 * BIAS_STG)   /* 223488 */

__global__ __launch_bounds__(512, 1) void k3_attn(const float* __restrict__ bias) {
    extern __shared__ char sm[];
    const uint32_t sbase = smem_u32(sm);
    float2* fcl = (float2*)(sm + FCL_OFF);        /* {f1, -m*log2e} per row */

    const int tid  = threadIdx.x;
    const int wid  = tid >> 5, lane = tid & 31;
    const int ibase = blockIdx.x * M_TILE;
    const int s     = blockIdx.y;
    const int jbase0 = s * JCHUNK;

    if (tid < M_TILE) {
        const float f1v = g_f1[ibase + tid];
        const float f2m = f2dec(g_f2maxu);
        const float x = f1v + f2m;
        fcl[tid] = make_float2(f1v, -fmaxf(x, 0.2f * x) * LOG2E);
    }
    __syncthreads();

    if (wid < 8) {
        /* ===================== PRODUCERS (256 thr) ===================== */
        /* warp w owns bias/P rows w*16 .. w*16+15; each lane covers 4 j   */
        const float* browbase[16];
#pragma unroll
        for (int q = 0; q < 16; ++q)
            browbase[q] = bias + (size_t)(ibase + wid * 16 + q) * N_TOK + lane * 4;

        /* prologue: prefetch bias tiles 0,1 into slots 0,1 */
#pragma unroll
        for (int pt = 0; pt < 2; ++pt) {
            const int jb2 = jbase0 + pt * JT;
            const uint32_t dbase = sbase + BIAS_OFF + pt * BIAS_STG
                                 + (wid * 16) * 512 + lane * 16;
#pragma unroll
            for (int q = 0; q < 16; ++q)
                CP_ASYNC16(dbase + q * 512, browbase[q] + jb2);
            CP_COMMIT();
        }

        int st2 = 0;
        for (int t = 0; t < NT_PER_CTA; ++t) {
            const int jb = jbase0 + t * JT;
            if (t >= 2) BAR_SYNC512(4 + st2);        /* P stage empty (t-2 done) */

            CP_WAIT1();                               /* own bias rows for tile t */
            __syncwarp();                             /* cross-lane visibility */

            /* generate P rows w*16..w*16+15: 128 j -> f16 via ex2.f16x2 */
            char* ph = sm + PH_OFF + st2 * PSTG;
            const char* bslot = sm + BIAS_OFF + (t & 1) * BIAS_STG;
            const float4 f2v = *((const float4*)(g_f2 + jb) + lane);
#pragma unroll
            for (int k = 0; k < 16; ++k) {
                const int i = wid * 16 + k;
                const float2 fc = fcl[i];
                const float4 bv = *(const float4*)(bslot + i * 512 + lane * 16);
                float x, t0, t1, t2, t3;
                x = fc.x + f2v.x; t0 = fmaxf(x, 0.2f * x);
                x = fc.x + f2v.y; t1 = fmaxf(x, 0.2f * x);
                x = fc.x + f2v.z; t2 = fmaxf(x, 0.2f * x);
                x = fc.x + f2v.w; t3 = fmaxf(x, 0.2f * x);
                const float g0 = fmaf(t0, LOG2E, fmaf(bv.x, LOG2E, fc.y));
                const float g1 = fmaf(t1, LOG2E, fmaf(bv.y, LOG2E, fc.y));
                const float g2 = fmaf(t2, LOG2E, fmaf(bv.z, LOG2E, fc.y));
                const float g3 = fmaf(t3, LOG2E, fmaf(bv.w, LOG2E, fc.y));
                *(uint2*)(ph + i * PSTRB + lane * 8) =
                    make_uint2(ex2h2(cvt2h(g0, g1)), ex2h2(cvt2h(g2, g3)));
            }

            /* prefetch tile t+2 into slot t&1 — safe: all LDS reads of the
               slot fed FFMAs that issued before these cp.async issue      */
            if (t + 2 < NT_PER_CTA) {
                const int jb2 = jbase0 + (t + 2) * JT;
                const uint32_t dbase = sbase + BIAS_OFF + (t & 1) * BIAS_STG
                                     + (wid * 16) * 512 + lane * 16;
#pragma unroll
                for (int q = 0; q < 16; ++q)
                    CP_ASYNC16(dbase + q * 512, browbase[q] + jb2);
            }
            CP_COMMIT();

            BAR_ARRIVE512(1 + st2);                  /* signal P full */
            st2 ^= 1;
        }
    } else {
        /* ===================== CONSUMERS (256 thr) ===================== */
        const int cw   = wid - 8;                    /* 0..7 */
        const int rg   = cw & 3;                     /* row group: 32 rows  */
        const int cg2  = cw >> 2;                    /* col group: 32 cols  */
        const int ctid = tid - 256;                  /* 0..255 */
        float acc[2][4][4];
        float accO[2][4];
#pragma unroll
        for (int b = 0; b < 2; ++b) {
#pragma unroll
            for (int n = 0; n < 4; ++n)
#pragma unroll
                for (int q = 0; q < 4; ++q) acc[b][n][q] = 0.f;
#pragma unroll
            for (int q = 0; q < 4; ++q) accO[b][q] = 0.f;
        }

        const uint32_t rsel = (uint32_t)(lane & 15) * PSTRB + (uint32_t)(lane >> 4) * 16;
        const uint32_t vhb = sbase + VH_OFF;

        /* init ones block: V rows 64..79 (col 64 = 1.0 across all k) */
        for (int u = ctid; u < 16 * 68; u += 256) {
            const int r = u / 68, w = u % 68;
            ((uint32_t*)(sm + VH_OFF + (64 + r) * PSTRB))[w] = (r == 0) ? 0x3C003C00u : 0u;
        }

        int st2 = 0;
        for (int t = 0; t < NT_PER_CTA; ++t) {
            const int jb = jbase0 + t * JT;

            /* issue V loads early (latency hides under the full-wait) */
            uint4 vh_r[4];
#pragma unroll
            for (int r = 0; r < 4; ++r) {
                const int u = r * 256 + ctid;
                const int c = u >> 4, q = u & 15;
                vh_r[r] = *((const uint4*)(g_ftsT + (size_t)c * N_TOK + jb) + q);
            }

            BAR_SYNC512(1 + st2);                    /* P full */

            /* stage V into (single) smem buffer */
#pragma unroll
            for (int r = 0; r < 4; ++r) {
                const int u = r * 256 + ctid;
                const int c = u >> 4, q = u & 15;
                *(uint4*)(sm + VH_OFF + c * PSTRB + q * 16) = vh_r[r];
            }
            BAR_SYNC256(8);                          /* V (+ones) visible */

            const uint32_t ph = sbase + PH_OFF + st2 * PSTG;

#pragma unroll
            for (int ks = 0; ks < 8; ++ks) {
                const uint32_t kofs = (uint32_t)ks * 32;   /* 16 f16 = 32B */
                uint32_t ah0[4], ah1[4];
                ldsm4(ah0[0], ah0[1], ah0[2], ah0[3],
                      ph + (rg * 32) * PSTRB + kofs + rsel);
                ldsm4(ah1[0], ah1[1], ah1[2], ah1[3],
                      ph + (rg * 32 + 16) * PSTRB + kofs + rsel);
                uint32_t b0[4], b1[4];
                ldsm4(b0[0], b0[1], b0[2], b0[3],
                      vhb + ((cg2 * 2) * 16) * PSTRB + kofs + rsel);
                ldsm4(b1[0], b1[1], b1[2], b1[3],
                      vhb + ((cg2 * 2 + 1) * 16) * PSTRB + kofs + rsel);
                mma16816(acc[0][0], ah0, b0[0], b0[2]);
                mma16816(acc[0][1], ah0, b0[1], b0[3]);
                mma16816(acc[0][2], ah0, b1[0], b1[2]);
                mma16816(acc[0][3], ah0, b1[1], b1[3]);
                mma16816(acc[1][0], ah1, b0[0], b0[2]);
                mma16816(acc[1][1], ah1, b0[1], b0[3]);
                mma16816(acc[1][2], ah1, b1[0], b1[2]);
                mma16816(acc[1][3], ah1, b1[1], b1[3]);
                if (cg2 == 1) {                      /* ones block: row sums */
                    uint32_t bo[4];
                    ldsm4(bo[0], bo[1], bo[2], bo[3],
                          vhb + 64 * PSTRB + kofs + rsel);
                    mma16816(accO[0], ah0, bo[0], bo[2]);
                    mma16816(accO[1], ah1, bo[0], bo[2]);
                }
            }
            BAR_ARRIVE512(4 + st2);                  /* signal P empty */
            st2 ^= 1;
        }

        /* write partials (rows rg*32.., cols cg2*32..) + denominators */
#pragma unroll
        for (int b = 0; b < 2; ++b) {
            const int m = rg * 32 + b * 16 + (lane >> 2);
            float* dst0 = g_acc + ((size_t)s * N_TOK + ibase + m) * OUTD;
            float* dst8 = dst0 + 8 * OUTD;
#pragma unroll
            for (int n = 0; n < 4; ++n) {
                const int c = cg2 * 32 + n * 8 + (lane & 3) * 2;
                *(float2*)(dst0 + c) = make_float2(acc[b][n][0], acc[b][n][1]);
                *(float2*)(dst8 + c) = make_float2(acc[b][n][2], acc[b][n][3]);
            }
            if (cg2 == 1 && (lane & 3) == 0) {
                g_den[(size_t)s * N_TOK + ibase + m]     = accO[b][0];
                g_den[(size_t)s * N_TOK + ibase + m + 8] = accO[b][2];
            }
        }
    }
}

/* ------------------------------------------------------------------ */
__global__ __launch_bounds__(256) void k4_combine(float* __restrict__ out) {
    const int idx = blockIdx.x * 256 + threadIdx.x;
    if (blockIdx.x == 0 && threadIdx.x == 0) g_f2maxu = 0u;  /* reset for next replay */
    if (idx >= N_TOK * 16) return;
    const int i = idx >> 4;
    float den = 0.f;
    float4 a = make_float4(0.f, 0.f, 0.f, 0.f);
#pragma unroll
    for (int s = 0; s < NSPLIT; ++s) {
        den += g_den[s * N_TOK + i];
        const float4 p = ((const float4*)g_acc)[(size_t)s * N_TOK * 16 + idx];
        a.x += p.x; a.y += p.y; a.z += p.z; a.w += p.w;
    }
    const float inv = 1.f / den;
    float4 r = make_float4(a.x * inv, a.y * inv, a.z * inv, a.w * inv);
    r.x = r.x > 0.f ? r.x : expm1f(r.x);
    r.y = r.y > 0.f ? r.y : expm1f(r.y);
    r.z = r.z > 0.f ? r.z : expm1f(r.z);
    r.w = r.w > 0.f ? r.w : expm1f(r.w);
    ((float4*)out)[idx] = r;
}

/* ------------------------------------------------------------------ */
extern "C" void kernel_launch(void* const* d_in, const int* in_sizes, int n_in,
                              void* d_out, int out_size) {
    const float* seq  = (const float*)d_in[0];
    const float* bias = (const float*)d_in[1];
    const float* W1   = (const float*)d_in[2];
    const float* a1   = (const float*)d_in[3];
    const float* b1   = (const float*)d_in[4];
    const float* a2   = (const float*)d_in[5];
    const float* b2   = (const float*)d_in[6];
    float* out = (float*)d_out;

    cudaFuncSetAttribute(k1_fts,  cudaFuncAttributeMaxDynamicSharedMemorySize, SMEM1_BYTES);
    cudaFuncSetAttribute(k3_attn, cudaFuncAttributeMaxDynamicSharedMemorySize, SMEM3_BYTES);

    k1_fts<<<128, 512, SMEM1_BYTES>>>(seq, W1, a1, b1, a2, b2);
    dim3 g3(N_TOK / M_TILE, NSPLIT);
    k3_attn<<<g3, 512, SMEM3_BYTES>>>(bias);
    k4_combine<<<(N_TOK * 16) / 256, 256>>>(out);
}